// round 7
// baseline (speedup 1.0000x reference)
#include <cuda_runtime.h>

// LSTM persistent kernel: B=256, T=512, I=3, H=256.
// Grid of 128 co-resident CTAs (8 hidden-tiles x 16 batch-tiles), W_hh slice
// resident in SMEM for all 512 steps, h exchanged via L2-resident double
// buffer, one global barrier (counter per step) per timestep.

#define Bsz 256
#define Tsz 512
#define Hsz 256
#define NI 3
#define HT 8            // hidden tiles (32 units each)
#define BT 16           // batch tiles (16 batches each)
#define NBLK (HT * BT)  // 128 CTAs
#define HU 32           // hidden units per CTA
#define GPC 128         // gate rows per CTA (4 types x 32 units)
#define BTILE 16
#define NTHR 256

// Persistent device scratch (no cudaMalloc allowed)
__device__ unsigned g_ctr[Tsz];                 // per-step barrier counters
__device__ float g_h[2][Bsz][Hsz];              // h exchange double buffer (512KB, L2-resident)
__device__ float g_xT[Tsz][Bsz][NI];            // time-major transposed input
__device__ float g_ypart[HT][Bsz][Tsz];         // per-hidden-tile partial y

struct Smem {
  float Ws[Hsz][GPC + 1];    // W_hh slice, k-major, padded (conflict-free)
  float hs[BTILE][Hsz];      // current h tile [b][k]
  float gate_s[4][HU][17];   // gate exchange [type][unit][b], padded
  float Wih_s[GPC][NI];
  float bias_s[GPC];         // b_ih + b_hh
  float x_s[BTILE][NI];
  float ys_s[16][BTILE];     // y partial reduction
};

__device__ __forceinline__ float fsigm(float x) {
  float e, r;
  asm("ex2.approx.f32 %0, %1;" : "=f"(e) : "f"(-1.4426950408889634f * x));
  asm("rcp.approx.f32 %0, %1;" : "=f"(r) : "f"(1.0f + e));
  return r;
}
__device__ __forceinline__ float ftanh(float x) {
  return fmaf(2.0f, fsigm(2.0f * x), -1.0f);
}

__global__ void init_kernel(const float* __restrict__ x) {
  int idx = blockIdx.x * blockDim.x + threadIdx.x;
  int stride = gridDim.x * blockDim.x;
  if (idx < Tsz) g_ctr[idx] = 0u;
  // zero h buffer 0 (initial hidden state)
  for (int i = idx; i < Bsz * Hsz; i += stride) ((float*)g_h)[i] = 0.0f;
  // transpose x[b][t][i] -> xT[t][b][i]
  for (int i = idx; i < Tsz * Bsz * NI; i += stride) {
    int t = i / (Bsz * NI);
    int r = i % (Bsz * NI);
    int b = r / NI;
    int ii = r % NI;
    ((float*)g_xT)[i] = x[(b * Tsz + t) * NI + ii];
  }
}

__global__ void __launch_bounds__(NTHR, 1) lstm_kernel(
    const float* __restrict__ W_ih, const float* __restrict__ W_hh,
    const float* __restrict__ b_ih, const float* __restrict__ b_hh,
    const float* __restrict__ W_lin) {
  extern __shared__ char smem_raw[];
  Smem& s = *reinterpret_cast<Smem*>(smem_raw);

  const int tid = threadIdx.x;
  const int lane = tid & 31;
  const int w = tid >> 5;        // 0..7
  const int wg = w & 1;          // gate-half of warp
  const int wb = w >> 1;         // batch-quarter of warp (0..3)
  const int ht = blockIdx.x & 7;
  const int bt = blockIdx.x >> 3;
  const int j0 = ht * HU;
  const int b0 = bt * BTILE;

  // ---- load W_hh slice transposed into SMEM (coalesced GMEM reads) ----
  for (int idx = tid; idx < GPC * Hsz; idx += NTHR) {
    int g = idx >> 8;            // gate row 0..127
    int k = idx & 255;           // consecutive k -> coalesced
    int row = (g >> 5) * Hsz + j0 + (g & 31);  // type = g/32, unit = g%32
    s.Ws[k][g] = W_hh[row * Hsz + k];
  }
  for (int g = tid; g < GPC; g += NTHR) {
    int row = (g >> 5) * Hsz + j0 + (g & 31);
    s.bias_s[g] = b_ih[row] + b_hh[row];
    s.Wih_s[g][0] = W_ih[row * NI + 0];
    s.Wih_s[g][1] = W_ih[row * NI + 1];
    s.Wih_s[g][2] = W_ih[row * NI + 2];
  }

  // epilogue assignment: thread -> (batch eb, units uq*2 .. uq*2+1)
  const int eb = tid & 15;
  const int uq = tid >> 4;  // 0..15
  float c_reg[2] = {0.0f, 0.0f};
  float wlin[2];
  wlin[0] = W_lin[j0 + uq * 2 + 0];
  wlin[1] = W_lin[j0 + uq * 2 + 1];
  __syncthreads();

  const int gA = wg * 64 + lane;  // gate type 2*wg,  unit = lane
  const int gB = gA + 32;         // gate type 2*wg+1, unit = lane

  for (int t = 0; t < Tsz; ++t) {
    // ---- stage h tile from global (L2) into SMEM ----
    const float4* hsrc = reinterpret_cast<const float4*>(&g_h[t & 1][b0][0]);
    float4* hdst = reinterpret_cast<float4*>(&s.hs[0][0]);
    #pragma unroll
    for (int i = 0; i < (BTILE * Hsz / 4) / NTHR; ++i)
      hdst[tid + i * NTHR] = __ldcg(&hsrc[tid + i * NTHR]);
    if (tid < BTILE * NI)
      (&s.x_s[0][0])[tid] = (&g_xT[t][b0][0])[tid];
    __syncthreads();

    // ---- accumulators init: bias + input contribution ----
    float acc0[4], acc1[4];
    #pragma unroll
    for (int j = 0; j < 4; ++j) {
      int b = wb * 4 + j;
      float x0 = s.x_s[b][0], x1 = s.x_s[b][1], x2 = s.x_s[b][2];
      acc0[j] = s.bias_s[gA] + x0 * s.Wih_s[gA][0] + x1 * s.Wih_s[gA][1] + x2 * s.Wih_s[gA][2];
      acc1[j] = s.bias_s[gB] + x0 * s.Wih_s[gB][0] + x1 * s.Wih_s[gB][1] + x2 * s.Wih_s[gB][2];
    }

    // ---- recurrent GEMM: lanes over gates (coalesced W), broadcast h ----
    const float4* hrow = reinterpret_cast<const float4*>(&s.hs[wb * 4][0]);
    #pragma unroll 2
    for (int k4 = 0; k4 < Hsz / 4; ++k4) {
      float4 hv[4];
      #pragma unroll
      for (int j = 0; j < 4; ++j) hv[j] = hrow[j * (Hsz / 4) + k4];
      #pragma unroll
      for (int kk = 0; kk < 4; ++kk) {
        float wA = s.Ws[k4 * 4 + kk][gA];
        float wB = s.Ws[k4 * 4 + kk][gB];
        #pragma unroll
        for (int j = 0; j < 4; ++j) {
          float hvk = (&hv[j].x)[kk];
          acc0[j] = fmaf(wA, hvk, acc0[j]);
          acc1[j] = fmaf(wB, hvk, acc1[j]);
        }
      }
    }

    // ---- exchange gates through SMEM ----
    #pragma unroll
    for (int j = 0; j < 4; ++j) {
      s.gate_s[2 * wg + 0][lane][wb * 4 + j] = acc0[j];
      s.gate_s[2 * wg + 1][lane][wb * 4 + j] = acc1[j];
    }
    __syncthreads();

    // ---- pointwise LSTM cell: 2 (b,u) outputs per thread ----
    float ysum = 0.0f;
    #pragma unroll
    for (int q = 0; q < 2; ++q) {
      int u = uq * 2 + q;
      float zi = s.gate_s[0][u][eb];
      float zf = s.gate_s[1][u][eb];
      float zg = s.gate_s[2][u][eb];
      float zo = s.gate_s[3][u][eb];
      float ig = fsigm(zi);
      float fg = fsigm(zf);
      float gg = ftanh(zg);
      float og = fsigm(zo);
      float c = fmaf(fg, c_reg[q], ig * gg);
      c_reg[q] = c;
      float h = og * ftanh(c);
      g_h[(t + 1) & 1][b0 + eb][j0 + u] = h;  // publish h (write-through to L2)
      ysum = fmaf(h, wlin[q], ysum);
    }
    s.ys_s[uq][eb] = ysum;
    __syncthreads();  // all h STGs + ys_s done

    // ---- barrier arrive (release), overlap y reduction with stragglers ----
    if (tid == 0) {
      asm volatile("red.release.gpu.global.add.u32 [%0], 1;"
                   :: "l"(&g_ctr[t]) : "memory");
    }
    if (tid < BTILE) {
      float acc = 0.0f;
      #pragma unroll
      for (int r = 0; r < 16; ++r) acc += s.ys_s[r][tid];
      g_ypart[ht][b0 + tid][t] = acc;
    }
    if (t + 1 < Tsz) {
      if (tid == 0) {
        unsigned v;
        do {
          asm volatile("ld.acquire.gpu.global.u32 %0, [%1];"
                       : "=r"(v) : "l"(&g_ctr[t]) : "memory");
        } while (v < NBLK);
      }
      __syncthreads();
    }
  }
}

__global__ void finish_kernel(float* __restrict__ y, const float* __restrict__ b_lin) {
  int idx = blockIdx.x * blockDim.x + threadIdx.x;  // idx = b*T + t
  if (idx >= Bsz * Tsz) return;
  int b = idx >> 9;
  int t = idx & 511;
  float acc = b_lin[0];
  #pragma unroll
  for (int p = 0; p < HT; ++p) acc += g_ypart[p][b][t];
  y[idx] = fmaxf(acc, 0.0f);
}

extern "C" void kernel_launch(void* const* d_in, const int* in_sizes, int n_in,
                              void* d_out, int out_size) {
  const float* x     = (const float*)d_in[0];
  const float* W_ih  = (const float*)d_in[1];
  const float* W_hh  = (const float*)d_in[2];
  const float* b_ih  = (const float*)d_in[3];
  const float* b_hh  = (const float*)d_in[4];
  const float* W_lin = (const float*)d_in[5];
  const float* b_lin = (const float*)d_in[6];
  float* y = (float*)d_out;

  cudaFuncSetAttribute(lstm_kernel, cudaFuncAttributeMaxDynamicSharedMemorySize,
                       (int)sizeof(Smem));
  init_kernel<<<256, 256>>>(x);
  lstm_kernel<<<NBLK, NTHR, sizeof(Smem)>>>(W_ih, W_hh, b_ih, b_hh, W_lin);
  finish_kernel<<<(Bsz * Tsz + 255) / 256, 256>>>(y, b_lin);
}

// round 14
// speedup vs baseline: 1.0451x; 1.0451x over previous
#include <cuda_runtime.h>

// LSTM persistent kernel: B=256, T=512, I=3, H=256.
// 128 co-resident CTAs (8 hidden-tiles x 16 batch-tiles), W_hh slice in SMEM,
// h exchanged via L2 double buffer.
// R7: per-batch-group (8-CTA) barriers instead of one 128-CTA grid barrier.
// R9: per-warp all-lane acquire spin, post-spin __syncthreads removed.

#define Bsz 256
#define Tsz 512
#define Hsz 256
#define NI 3
#define HT 8            // hidden tiles (32 units each)
#define BT 16           // batch tiles (16 batches each)
#define NBLK (HT * BT)  // 128 CTAs
#define HU 32           // hidden units per CTA
#define GPC 128         // gate rows per CTA (4 types x 32 units)
#define BTILE 16
#define NTHR 256

// Persistent device scratch (no cudaMalloc allowed)
__device__ unsigned g_ctr[BT][Tsz];             // per-(group,step) barrier counters
__device__ float g_h[2][Bsz][Hsz];              // h exchange double buffer (512KB, L2-resident)
__device__ float g_xT[Tsz][Bsz][NI];            // time-major transposed input
__device__ float g_ypart[HT][Bsz][Tsz];         // per-hidden-tile partial y

struct Smem {
  float Ws[Hsz][GPC + 1];    // W_hh slice, k-major, padded (conflict-free)
  float hs[BTILE][Hsz];      // current h tile [b][k]
  float gate_s[4][HU][17];   // gate exchange [type][unit][b], padded
  float Wih_s[GPC][NI];
  float bias_s[GPC];         // b_ih + b_hh
  float x_s[BTILE][NI];
  float ys_s[16][BTILE];     // y partial reduction
};

__device__ __forceinline__ float fsigm(float x) {
  float e, r;
  asm("ex2.approx.f32 %0, %1;" : "=f"(e) : "f"(-1.4426950408889634f * x));
  asm("rcp.approx.f32 %0, %1;" : "=f"(r) : "f"(1.0f + e));
  return r;
}
__device__ __forceinline__ float ftanh(float x) {
  return fmaf(2.0f, fsigm(2.0f * x), -1.0f);
}

__global__ void init_kernel(const float* __restrict__ x) {
  int idx = blockIdx.x * blockDim.x + threadIdx.x;
  int stride = gridDim.x * blockDim.x;
  for (int i = idx; i < BT * Tsz; i += stride) ((unsigned*)g_ctr)[i] = 0u;
  // zero h buffer 0 (initial hidden state)
  for (int i = idx; i < Bsz * Hsz; i += stride) ((float*)g_h)[i] = 0.0f;
  // transpose x[b][t][i] -> xT[t][b][i]
  for (int i = idx; i < Tsz * Bsz * NI; i += stride) {
    int t = i / (Bsz * NI);
    int r = i % (Bsz * NI);
    int b = r / NI;
    int ii = r % NI;
    ((float*)g_xT)[i] = x[(b * Tsz + t) * NI + ii];
  }
}

__global__ void __launch_bounds__(NTHR, 1) lstm_kernel(
    const float* __restrict__ W_ih, const float* __restrict__ W_hh,
    const float* __restrict__ b_ih, const float* __restrict__ b_hh,
    const float* __restrict__ W_lin) {
  extern __shared__ char smem_raw[];
  Smem& s = *reinterpret_cast<Smem*>(smem_raw);

  const int tid = threadIdx.x;
  const int lane = tid & 31;
  const int w = tid >> 5;        // 0..7
  const int wg = w & 1;          // gate-half of warp
  const int wb = w >> 1;         // batch-quarter of warp (0..3)
  const int ht = blockIdx.x & 7;
  const int bt = blockIdx.x >> 3;
  const int j0 = ht * HU;
  const int b0 = bt * BTILE;

  // ---- load W_hh slice transposed into SMEM (coalesced GMEM reads) ----
  for (int idx = tid; idx < GPC * Hsz; idx += NTHR) {
    int g = idx >> 8;            // gate row 0..127
    int k = idx & 255;           // consecutive k -> coalesced
    int row = (g >> 5) * Hsz + j0 + (g & 31);  // type = g/32, unit = g%32
    s.Ws[k][g] = W_hh[row * Hsz + k];
  }
  for (int g = tid; g < GPC; g += NTHR) {
    int row = (g >> 5) * Hsz + j0 + (g & 31);
    s.bias_s[g] = b_ih[row] + b_hh[row];
    s.Wih_s[g][0] = W_ih[row * NI + 0];
    s.Wih_s[g][1] = W_ih[row * NI + 1];
    s.Wih_s[g][2] = W_ih[row * NI + 2];
  }

  // epilogue assignment: thread -> (batch eb, units uq*2 .. uq*2+1)
  const int eb = tid & 15;
  const int uq = tid >> 4;  // 0..15
  float c_reg[2] = {0.0f, 0.0f};
  float wlin[2];
  wlin[0] = W_lin[j0 + uq * 2 + 0];
  wlin[1] = W_lin[j0 + uq * 2 + 1];
  __syncthreads();

  const int gA = wg * 64 + lane;  // gate type 2*wg,  unit = lane
  const int gB = gA + 32;         // gate type 2*wg+1, unit = lane

  for (int t = 0; t < Tsz; ++t) {
    // ---- stage h tile from global (L2) into SMEM ----
    const float4* hsrc = reinterpret_cast<const float4*>(&g_h[t & 1][b0][0]);
    float4* hdst = reinterpret_cast<float4*>(&s.hs[0][0]);
    #pragma unroll
    for (int i = 0; i < (BTILE * Hsz / 4) / NTHR; ++i)
      hdst[tid + i * NTHR] = __ldcg(&hsrc[tid + i * NTHR]);
    if (tid < BTILE * NI)
      (&s.x_s[0][0])[tid] = (&g_xT[t][b0][0])[tid];
    __syncthreads();

    // ---- accumulators init: bias + input contribution ----
    float acc0[4], acc1[4];
    #pragma unroll
    for (int j = 0; j < 4; ++j) {
      int b = wb * 4 + j;
      float x0 = s.x_s[b][0], x1 = s.x_s[b][1], x2 = s.x_s[b][2];
      acc0[j] = s.bias_s[gA] + x0 * s.Wih_s[gA][0] + x1 * s.Wih_s[gA][1] + x2 * s.Wih_s[gA][2];
      acc1[j] = s.bias_s[gB] + x0 * s.Wih_s[gB][0] + x1 * s.Wih_s[gB][1] + x2 * s.Wih_s[gB][2];
    }

    // ---- recurrent GEMM: lanes over gates (coalesced W), broadcast h ----
    const float4* hrow = reinterpret_cast<const float4*>(&s.hs[wb * 4][0]);
    #pragma unroll 2
    for (int k4 = 0; k4 < Hsz / 4; ++k4) {
      float4 hv[4];
      #pragma unroll
      for (int j = 0; j < 4; ++j) hv[j] = hrow[j * (Hsz / 4) + k4];
      #pragma unroll
      for (int kk = 0; kk < 4; ++kk) {
        float wA = s.Ws[k4 * 4 + kk][gA];
        float wB = s.Ws[k4 * 4 + kk][gB];
        #pragma unroll
        for (int j = 0; j < 4; ++j) {
          float hvk = (&hv[j].x)[kk];
          acc0[j] = fmaf(wA, hvk, acc0[j]);
          acc1[j] = fmaf(wB, hvk, acc1[j]);
        }
      }
    }

    // ---- exchange gates through SMEM ----
    #pragma unroll
    for (int j = 0; j < 4; ++j) {
      s.gate_s[2 * wg + 0][lane][wb * 4 + j] = acc0[j];
      s.gate_s[2 * wg + 1][lane][wb * 4 + j] = acc1[j];
    }
    __syncthreads();

    // ---- pointwise LSTM cell: 2 (b,u) outputs per thread ----
    float ysum = 0.0f;
    #pragma unroll
    for (int q = 0; q < 2; ++q) {
      int u = uq * 2 + q;
      float zi = s.gate_s[0][u][eb];
      float zf = s.gate_s[1][u][eb];
      float zg = s.gate_s[2][u][eb];
      float zo = s.gate_s[3][u][eb];
      float ig = fsigm(zi);
      float fg = fsigm(zf);
      float gg = ftanh(zg);
      float og = fsigm(zo);
      float c = fmaf(fg, c_reg[q], ig * gg);
      c_reg[q] = c;
      float h = og * ftanh(c);
      g_h[(t + 1) & 1][b0 + eb][j0 + u] = h;  // publish h (write-through to L2)
      ysum = fmaf(h, wlin[q], ysum);
    }
    s.ys_s[uq][eb] = ysum;
    __syncthreads();  // all h STGs + ys_s done

    // ---- group barrier arrive (release); overlap y reduction with wait ----
    if (tid == 0) {
      asm volatile("red.release.gpu.global.add.u32 [%0], 1;"
                   :: "l"(&g_ctr[bt][t]) : "memory");
    }
    if (tid < BTILE) {
      float acc = 0.0f;
      #pragma unroll
      for (int r = 0; r < 16; ++r) acc += s.ys_s[r][tid];
      g_ypart[ht][b0 + tid][t] = acc;
    }
    if (t + 1 < Tsz) {
      // Per-warp spin: every lane acquires the counter (coalesced to one L2
      // request). No post-spin __syncthreads — the staging sync at the top of
      // the next iteration re-converges the CTA, and s.hs is dead here.
      unsigned v;
      do {
        asm volatile("ld.acquire.gpu.global.u32 %0, [%1];"
                     : "=r"(v) : "l"(&g_ctr[bt][t]) : "memory");
      } while (v < HT);   // wait only for the 8 CTAs of this batch group
    }
  }
}

__global__ void finish_kernel(float* __restrict__ y, const float* __restrict__ b_lin) {
  int idx = blockIdx.x * blockDim.x + threadIdx.x;  // idx = b*T + t
  if (idx >= Bsz * Tsz) return;
  int b = idx >> 9;
  int t = idx & 511;
  float acc = b_lin[0];
  #pragma unroll
  for (int p = 0; p < HT; ++p) acc += g_ypart[p][b][t];
  y[idx] = fmaxf(acc, 0.0f);
}

extern "C" void kernel_launch(void* const* d_in, const int* in_sizes, int n_in,
                              void* d_out, int out_size) {
  const float* x     = (const float*)d_in[0];
  const float* W_ih  = (const float*)d_in[1];
  const float* W_hh  = (const float*)d_in[2];
  const float* b_ih  = (const float*)d_in[3];
  const float* b_hh  = (const float*)d_in[4];
  const float* W_lin = (const float*)d_in[5];
  const float* b_lin = (const float*)d_in[6];
  float* y = (float*)d_out;

  cudaFuncSetAttribute(lstm_kernel, cudaFuncAttributeMaxDynamicSharedMemorySize,
                       (int)sizeof(Smem));
  init_kernel<<<256, 256>>>(x);
  lstm_kernel<<<NBLK, NTHR, sizeof(Smem)>>>(W_ih, W_hh, b_ih, b_hh, W_lin);
  finish_kernel<<<(Bsz * Tsz + 255) / 256, 256>>>(y, b_lin);
}